// round 8
// baseline (speedup 1.0000x reference)
#include <cuda_runtime.h>
#include <cuda_fp16.h>
#include <cstdint>

#define N_NODESC 50000
#define N_EDGESC 400000
#define HID 200
#define HID4 50
#define NG 64
#define NOUT 16
#define NL 5
#define AROWS 104   // padded u32 (half2) row stride for fp16 activations

// ---------------- scratch (static __device__, no allocation) ----------------
static __device__ float g_x[N_NODESC * HID];                      // fp32 node features
static __device__ __align__(16) uint32_t g_x16[N_NODESC * AROWS]; // fp16x2 copy of x (gather src)
static __device__ __align__(16) uint32_t g_h16[N_NODESC * AROWS]; // fp16x2 agg output
static __device__ __align__(16) uint32_t g_t16[N_NODESC * AROWS]; // fp16x2 GEMM1 output
static __device__ __align__(16) uint32_t g_wp[10 * 13 * HID * 8]; // packed weights [mid][t][n][kk]
static __device__ __align__(8) uint32_t g_etab16[60 * 100];       // fp16x2 edge-emb table
static __device__ float g_alpha[NL * HID];
static __device__ float g_beta[NL * HID];
static __device__ int   g_deg[N_NODESC];
static __device__ int   g_off[N_NODESC + 1];
static __device__ int   g_cur[N_NODESC];
static __device__ int   g_packed[N_EDGESC];
static __device__ float g_pooled[(NL + 1) * NG * HID];
static __device__ int   g_counts[NG];

// ---------------- helpers ----------------
__device__ __forceinline__ uint32_t pack_f16x2(float even, float odd) {
    uint32_t r;
    asm("cvt.rn.f16x2.f32 %0, %1, %2;" : "=r"(r) : "f"(odd), "f"(even));
    return r;
}
__device__ __forceinline__ float2 h2f(uint32_t u) {
    __half2 h = *(__half2*)&u;
    return __half22float2(h);
}

__device__ __forceinline__ void mma_f16(float* c, uint32_t a0, uint32_t a1,
                                        uint32_t a2, uint32_t a3,
                                        uint32_t b0, uint32_t b1) {
    asm volatile(
        "mma.sync.aligned.m16n8k16.row.col.f32.f16.f16.f32 "
        "{%0,%1,%2,%3}, {%4,%5,%6,%7}, {%8,%9}, {%0,%1,%2,%3};\n"
        : "+f"(c[0]), "+f"(c[1]), "+f"(c[2]), "+f"(c[3])
        : "r"(a0), "r"(a1), "r"(a2), "r"(a3), "r"(b0), "r"(b1));
}

__device__ __forceinline__ void cp16(void* dst_smem, const void* src, bool full) {
    uint32_t d = (uint32_t)__cvta_generic_to_shared(dst_smem);
    int sz = full ? 16 : 0;
    asm volatile("cp.async.cg.shared.global [%0], [%1], 16, %2;\n"
                 :: "r"(d), "l"(src), "r"(sz) : "memory");
}

// ---------------- merged setup kernel ----------------
__global__ void setup_kernel(const float* __restrict__ bn_g, const float* __restrict__ bn_b,
                             const float* __restrict__ bn_m, const float* __restrict__ bn_v,
                             const float* __restrict__ b1,
                             const float* __restrict__ etype_emb, const float* __restrict__ epos_emb) {
    int i = blockIdx.x * blockDim.x + threadIdx.x;
    if (i < N_NODESC) { g_deg[i] = 0; g_cur[i] = 0; }
    if (i < NG) g_counts[i] = 0;
    if (i < NL * HID) {
        float a = bn_g[i] * rsqrtf(bn_v[i] + 1e-5f);
        g_alpha[i] = a;
        g_beta[i] = (b1[i] - bn_m[i]) * a + bn_b[i];
    }
    if (i < 60 * 100) {
        int e = i / 100, j = (i % 100) * 2;
        int et = e / 20, ep = e % 20;
        float v0 = etype_emb[et * HID + j] + epos_emb[ep * HID + j];
        float v1 = etype_emb[et * HID + j + 1] + epos_emb[ep * HID + j + 1];
        g_etab16[i] = pack_f16x2(v0, v1);
    }
    int stride = gridDim.x * blockDim.x;
    for (int j = i; j < (NL + 1) * NG * HID; j += stride) g_pooled[j] = 0.f;
}

__global__ void node_emb_kernel(const int* __restrict__ kind, const int* __restrict__ content,
                                const float* __restrict__ kemb, const float* __restrict__ i2v,
                                const float* __restrict__ temb) {
    int n = blockIdx.x * 4 + (threadIdx.x >> 6);
    int t = threadIdx.x & 63;
    if (t >= HID4 || n >= N_NODESC) return;
    int k = kind[n];
    const float4* k4 = (const float4*)(kemb + k * HID);
    float4 v = k4[t];
    float4 w;
    if (k == 0) w = ((const float4*)(i2v + content[n] * HID))[t];
    else        w = ((const float4*)temb)[t];
    v.x += w.x; v.y += w.y; v.z += w.z; v.w += w.w;
    ((float4*)g_x)[n * HID4 + t] = v;
    g_x16[(size_t)n * AROWS + 2 * t]     = pack_f16x2(v.x, v.y);
    g_x16[(size_t)n * AROWS + 2 * t + 1] = pack_f16x2(v.z, v.w);
}

// pack weights: g_wp[mid][t][n][kk] = half2(W[16t+2kk][n], W[16t+2kk+1][n]); mid = l*2+m
__global__ void wpack_kernel(const float* __restrict__ W1, const float* __restrict__ W2) {
    int idx = blockIdx.x * blockDim.x + threadIdx.x;
    if (idx >= 10 * 13 * HID * 8) return;
    int mid = idx / (13 * HID * 8);
    int rem = idx % (13 * HID * 8);
    int t = rem / (HID * 8);
    int rem2 = rem % (HID * 8);
    int n = rem2 >> 3;
    int kk = rem2 & 7;
    int l = mid >> 1, m = mid & 1;
    const float* W = (m == 0) ? (W1 + l * HID * HID) : (W2 + l * HID * HID);
    int k0 = t * 16 + 2 * kk;
    float v0 = (k0 < HID) ? W[k0 * HID + n] : 0.f;
    float v1 = (k0 + 1 < HID) ? W[(k0 + 1) * HID + n] : 0.f;
    g_wp[idx] = pack_f16x2(v0, v1);
}

// ---------------- CSR build ----------------
__global__ void hist_kernel(const int* __restrict__ dst, const int* __restrict__ batch) {
    int j = blockIdx.x * blockDim.x + threadIdx.x;
    if (j < N_EDGESC) atomicAdd(&g_deg[dst[j]], 1);
    if (j < N_NODESC) atomicAdd(&g_counts[batch[j]], 1);
}

__global__ void scan_kernel() {
    __shared__ int wsum[32];
    __shared__ int carry;
    int lt = threadIdx.x, lane = lt & 31, w = lt >> 5;
    if (lt == 0) { carry = 0; g_off[0] = 0; }
    __syncthreads();
    for (int base = 0; base < N_NODESC; base += 4096) {
        int i = base + lt * 4;
        int v0 = (i + 0 < N_NODESC) ? g_deg[i + 0] : 0;
        int v1 = (i + 1 < N_NODESC) ? g_deg[i + 1] : 0;
        int v2 = (i + 2 < N_NODESC) ? g_deg[i + 2] : 0;
        int v3 = (i + 3 < N_NODESC) ? g_deg[i + 3] : 0;
        int s0 = v0, s1 = s0 + v1, s2 = s1 + v2, s3 = s2 + v3;
        int tsc = s3;
#pragma unroll
        for (int o = 1; o < 32; o <<= 1) {
            int u = __shfl_up_sync(0xffffffffu, tsc, o);
            if (lane >= o) tsc += u;
        }
        if (lane == 31) wsum[w] = tsc;
        int texc = tsc - s3;
        __syncthreads();
        if (w == 0) {
            int ws = wsum[lane];
#pragma unroll
            for (int o = 1; o < 32; o <<= 1) {
                int u = __shfl_up_sync(0xffffffffu, ws, o);
                if (lane >= o) ws += u;
            }
            wsum[lane] = ws;
        }
        __syncthreads();
        int wexc = (w == 0) ? 0 : wsum[w - 1];
        int off = carry + wexc + texc;
        if (i + 0 < N_NODESC) g_off[i + 1] = off + s0;
        if (i + 1 < N_NODESC) g_off[i + 2] = off + s1;
        if (i + 2 < N_NODESC) g_off[i + 3] = off + s2;
        if (i + 3 < N_NODESC) g_off[i + 4] = off + s3;
        __syncthreads();
        if (lt == 0) carry = carry + wsum[31];
        __syncthreads();
    }
}

__global__ void scatter_kernel(const int* __restrict__ src, const int* __restrict__ dst,
                               const int* __restrict__ etype, const int* __restrict__ epos) {
    int j = blockIdx.x * blockDim.x + threadIdx.x;
    if (j >= N_EDGESC) return;
    int d = dst[j];
    int pos = g_off[d] + atomicAdd(&g_cur[d], 1);
    int ep = epos[j]; if (ep > 19) ep = 19;
    int ei = etype[j] * 20 + ep;
    g_packed[pos] = src[j] | (ei << 16);
}

// ---------------- per-layer kernels ----------------
__device__ __forceinline__ void acc4(float4& a, float4 b) {
    a.x += b.x; a.y += b.y; a.z += b.z; a.w += b.w;
}

// fp16 gather message: relu(x16[src] + etab16[ei]) accumulated in fp32
__device__ __forceinline__ void msg_acc(float4& acc, uint2 xs, uint2 es) {
    float2 x0 = h2f(xs.x), x1 = h2f(xs.y);
    float2 e0 = h2f(es.x), e1 = h2f(es.y);
    acc.x += fmaxf(x0.x + e0.x, 0.f);
    acc.y += fmaxf(x0.y + e0.y, 0.f);
    acc.z += fmaxf(x1.x + e1.x, 0.f);
    acc.w += fmaxf(x1.y + e1.y, 0.f);
}

// h16[n] = fp16(x[n] + sum relu(x16[src]+etab16)); 4 nodes/block, lane=4 values
__global__ void __launch_bounds__(256) aggregate_kernel() {
    int n = blockIdx.x * 4 + (threadIdx.x >> 6);
    int t = threadIdx.x & 63;
    if (n >= N_NODESC) return;
    if (t >= 54) return;
    if (t >= HID4) {                       // zero-pad u32 cols [100,104)
        g_h16[(size_t)n * AROWS + 50 + t] = 0;
        return;
    }
    const float4* __restrict__ x4 = (const float4*)g_x;
    float4 acc = x4[n * HID4 + t];         // self term in fp32
    int s0 = g_off[n], s1 = g_off[n + 1];
    int k = s0;
    for (; k + 3 < s1; k += 4) {
        int p0 = g_packed[k], p1 = g_packed[k + 1];
        int p2 = g_packed[k + 2], p3 = g_packed[k + 3];
        uint2 xa = *(const uint2*)&g_x16[(size_t)(p0 & 0xFFFF) * AROWS + 2 * t];
        uint2 ea = *(const uint2*)&g_etab16[(p0 >> 16) * 100 + 2 * t];
        uint2 xb = *(const uint2*)&g_x16[(size_t)(p1 & 0xFFFF) * AROWS + 2 * t];
        uint2 eb = *(const uint2*)&g_etab16[(p1 >> 16) * 100 + 2 * t];
        uint2 xc = *(const uint2*)&g_x16[(size_t)(p2 & 0xFFFF) * AROWS + 2 * t];
        uint2 ec = *(const uint2*)&g_etab16[(p2 >> 16) * 100 + 2 * t];
        uint2 xd = *(const uint2*)&g_x16[(size_t)(p3 & 0xFFFF) * AROWS + 2 * t];
        uint2 ed = *(const uint2*)&g_etab16[(p3 >> 16) * 100 + 2 * t];
        msg_acc(acc, xa, ea);
        msg_acc(acc, xb, eb);
        msg_acc(acc, xc, ec);
        msg_acc(acc, xd, ed);
    }
    for (; k < s1; k++) {
        int p = g_packed[k];
        uint2 xs = *(const uint2*)&g_x16[(size_t)(p & 0xFFFF) * AROWS + 2 * t];
        uint2 es = *(const uint2*)&g_etab16[(p >> 16) * 100 + 2 * t];
        msg_acc(acc, xs, es);
    }
    uint32_t* h = g_h16 + (size_t)n * AROWS;
    h[2 * t]     = pack_f16x2(acc.x, acc.y);
    h[2 * t + 1] = pack_f16x2(acc.z, acc.w);
}

// ---------------- FP16 tensor-core GEMM, cp.async 3-stage pipeline ----------------
// MODE 0: A=g_h16, out=g_t16 (fp16, BN-folded epilogue + relu)
// MODE 1: A=g_t16, out=g_x + g_x16 (fp32 + fp16, bias epilogue + relu)
template <int MODE>
__global__ void __launch_bounds__(256, 2) gemm_tc_kernel(const uint32_t* __restrict__ Wp,
                                                         const float* __restrict__ bias,
                                                         int layer) {
    const uint32_t* __restrict__ A = (MODE == 0) ? g_h16 : g_t16;

    __shared__ __align__(16) uint32_t As[3][128][12];
    __shared__ __align__(16) uint32_t Bs[3][104][12];

    const int tid = threadIdx.x;
    const int warp = tid >> 5, lane = tid & 31;
    const int grp = lane >> 2, qid = lane & 3;
    const int row0 = blockIdx.x * 128;
    const int col0 = blockIdx.y * 104;
    const int NT = (blockIdx.y == 0) ? 13 : 12;
    const int NC = NT * 8;
    const int ar = warp * 16 + grp;

    const int a_r = tid >> 1, a_half = tid & 1;
    const bool a_ok = (row0 + a_r) < N_NODESC;
    int a_row = a_ok ? (row0 + a_r) : (N_NODESC - 1);
    const uint32_t* a_src0 = A + (size_t)a_row * AROWS + a_half * 4;
    const int b_n = tid >> 1, b_half = tid & 1;
    const bool b_act = tid < 2 * NC;
    const uint32_t* b_src0 = Wp + (size_t)(col0 + (b_act ? b_n : 0)) * 8 + b_half * 4;

    float acc[13][4];
#pragma unroll
    for (int nt = 0; nt < 13; nt++)
#pragma unroll
        for (int j = 0; j < 4; j++) acc[nt][j] = 0.f;

#define ISSUE(T, S)                                                             \
    do {                                                                        \
        cp16(&As[S][a_r][a_half * 4], a_src0 + 8 * (T), a_ok);                  \
        if (b_act) cp16(&Bs[S][b_n][b_half * 4], b_src0 + (size_t)(T) * (HID * 8), true); \
        asm volatile("cp.async.commit_group;\n" ::: "memory");                  \
    } while (0)

    ISSUE(0, 0);
    ISSUE(1, 1);

    for (int t = 0; t < 13; t++) {
        const int s = t % 3;
        if (t < 12) asm volatile("cp.async.wait_group 1;\n" ::: "memory");
        else        asm volatile("cp.async.wait_group 0;\n" ::: "memory");
        __syncthreads();
        if (t + 2 < 13) ISSUE(t + 2, (t + 2) % 3);

        uint32_t a0 = As[s][ar][qid];
        uint32_t a1 = As[s][ar + 8][qid];
        uint32_t a2 = As[s][ar][qid + 4];
        uint32_t a3 = As[s][ar + 8][qid + 4];
#pragma unroll
        for (int nt = 0; nt < 13; nt++) {
            if (nt < NT) {
                int n = nt * 8 + grp;
                uint32_t b0 = Bs[s][n][qid];
                uint32_t b1 = Bs[s][n][qid + 4];
                mma_f16(acc[nt], a0, a1, a2, a3, b0, b1);
            }
        }
    }
#undef ISSUE

    // ---- epilogue ----
    int r = row0 + warp * 16 + grp;
    bool ok0 = r < N_NODESC;
    bool ok1 = (r + 8) < N_NODESC;
    const float* abase = g_alpha + layer * HID;
    const float* bbase = g_beta + layer * HID;
#pragma unroll
    for (int nt = 0; nt < 13; nt++) {
        if (nt < NT) {
            int col = col0 + nt * 8 + 2 * qid;
            float v0 = acc[nt][0], v1 = acc[nt][1];
            float v2 = acc[nt][2], v3 = acc[nt][3];
            if (MODE == 0) {
                float a0 = abase[col], a1 = abase[col + 1];
                float bb0 = bbase[col], bb1 = bbase[col + 1];
                v0 = v0 * a0 + bb0; v1 = v1 * a1 + bb1;
                v2 = v2 * a0 + bb0; v3 = v3 * a1 + bb1;
            } else {
                float bi0 = bias[col], bi1 = bias[col + 1];
                v0 += bi0; v1 += bi1; v2 += bi0; v3 += bi1;
            }
            v0 = fmaxf(v0, 0.f); v1 = fmaxf(v1, 0.f);
            v2 = fmaxf(v2, 0.f); v3 = fmaxf(v3, 0.f);
            if (MODE == 0) {
                if (ok0) g_t16[(size_t)r * AROWS + (col >> 1)] = pack_f16x2(v0, v1);
                if (ok1) g_t16[(size_t)(r + 8) * AROWS + (col >> 1)] = pack_f16x2(v2, v3);
            } else {
                if (ok0) {
                    *(float2*)(g_x + (size_t)r * HID + col) = make_float2(v0, v1);
                    g_x16[(size_t)r * AROWS + (col >> 1)] = pack_f16x2(v0, v1);
                }
                if (ok1) {
                    *(float2*)(g_x + (size_t)(r + 8) * HID + col) = make_float2(v2, v3);
                    g_x16[(size_t)(r + 8) * AROWS + (col >> 1)] = pack_f16x2(v2, v3);
                }
            }
        }
    }
    // zero-pad g_t16 tail cols
    if (MODE == 0 && blockIdx.y == 0 && tid < 128 && (row0 + tid) < N_NODESC) {
        uint4 z = make_uint4(0, 0, 0, 0);
        *(uint4*)&g_t16[(size_t)(row0 + tid) * AROWS + 100] = z;
    }
}

// run-accumulated segment-sum pooling over sorted batch_vec (float4 lanes)
__global__ void __launch_bounds__(64) pool_kernel(const int* __restrict__ batch, int layer) {
    int t = threadIdx.x;
    if (t >= HID4) return;
    int i0 = blockIdx.x * 64;
    int i1 = i0 + 64; if (i1 > N_NODESC) i1 = N_NODESC;
    if (i0 >= N_NODESC) return;
    const float4* __restrict__ x4 = (const float4*)g_x;
    float* pooled = g_pooled + layer * NG * HID;
    float4 acc = make_float4(0.f, 0.f, 0.f, 0.f);
    int cur = batch[i0];
    for (int i = i0; i < i1; i++) {
        int g = batch[i];
        if (g != cur) {
            float* p = pooled + cur * HID + t * 4;
            atomicAdd(p + 0, acc.x); atomicAdd(p + 1, acc.y);
            atomicAdd(p + 2, acc.z); atomicAdd(p + 3, acc.w);
            acc = make_float4(0.f, 0.f, 0.f, 0.f);
            cur = g;
        }
        acc4(acc, x4[i * HID4 + t]);
    }
    float* p = pooled + cur * HID + t * 4;
    atomicAdd(p + 0, acc.x); atomicAdd(p + 1, acc.y);
    atomicAdd(p + 2, acc.z); atomicAdd(p + 3, acc.w);
}

__global__ void final_kernel(const float* __restrict__ fcW, const float* __restrict__ fcb,
                             float* __restrict__ out) {
    __shared__ float red[256];
    int g = blockIdx.x;
    int t = threadIdx.x;
    int o = t & 15, seg = t >> 4;
    float acc = 0.f;
    for (int i = 0; i < NL + 1; i++) {
        const float* p = g_pooled + (i * NG + g) * HID;
        const float* w = fcW + i * HID * NOUT;
        for (int tt = seg; tt < HID; tt += 16)
            acc += p[tt] * w[tt * NOUT + o];
    }
    red[t] = acc;
    __syncthreads();
    for (int s = 8; s >= 1; s >>= 1) {
        if (seg < s) red[t] += red[t + s * 16];
        __syncthreads();
    }
    if (seg == 0) {
        float bias = 0.f;
        for (int i = 0; i < NL + 1; i++) bias += fcb[i * NOUT + o];
        float cnt = fmaxf((float)g_counts[g], 1.f);
        out[g * NOUT + o] = red[o] / cnt + bias;
    }
}

// ---------------- launch ----------------
extern "C" void kernel_launch(void* const* d_in, const int* in_sizes, int n_in,
                              void* d_out, int out_size) {
    (void)in_sizes; (void)n_in; (void)out_size;
    const int* node_kind    = (const int*)d_in[0];
    const int* node_content = (const int*)d_in[1];
    const int* edge_index   = (const int*)d_in[2];
    const int* edge_type    = (const int*)d_in[3];
    const int* edge_pos     = (const int*)d_in[4];
    const int* batch_vec    = (const int*)d_in[5];
    const float* kind_emb   = (const float*)d_in[6];
    const float* inst2vec   = (const float*)d_in[7];
    const float* type_emb   = (const float*)d_in[8];
    const float* etype_emb  = (const float*)d_in[9];
    const float* epos_emb   = (const float*)d_in[10];
    const float* W1         = (const float*)d_in[11];
    const float* b1         = (const float*)d_in[12];
    const float* bn_g       = (const float*)d_in[13];
    const float* bn_b       = (const float*)d_in[14];
    const float* bn_m       = (const float*)d_in[15];
    const float* bn_v       = (const float*)d_in[16];
    const float* W2         = (const float*)d_in[17];
    const float* b2         = (const float*)d_in[18];
    const float* fc_W       = (const float*)d_in[19];
    const float* fc_b       = (const float*)d_in[20];
    float* out = (float*)d_out;

    const int* src = edge_index;
    const int* dst = edge_index + N_EDGESC;

    setup_kernel<<<(N_NODESC + 255) / 256, 256>>>(bn_g, bn_b, bn_m, bn_v, b1, etype_emb, epos_emb);
    node_emb_kernel<<<(N_NODESC + 3) / 4, 256>>>(node_kind, node_content, kind_emb, inst2vec, type_emb);
    wpack_kernel<<<(10 * 13 * HID * 8 + 255) / 256, 256>>>(W1, W2);

    hist_kernel<<<(N_EDGESC + 255) / 256, 256>>>(dst, batch_vec);
    scan_kernel<<<1, 1024>>>();
    scatter_kernel<<<(N_EDGESC + 255) / 256, 256>>>(src, dst, edge_type, edge_pos);

    uint32_t* wp = nullptr;
    cudaGetSymbolAddress((void**)&wp, g_wp);

    dim3 ggrid((N_NODESC + 127) / 128, 2);
    pool_kernel<<<(N_NODESC + 63) / 64, 64>>>(batch_vec, 0);
    for (int l = 0; l < NL; l++) {
        aggregate_kernel<<<(N_NODESC + 3) / 4, 256>>>();
        gemm_tc_kernel<0><<<ggrid, 256>>>(wp + (size_t)(l * 2 + 0) * 13 * HID * 8, nullptr, l);
        gemm_tc_kernel<1><<<ggrid, 256>>>(wp + (size_t)(l * 2 + 1) * 13 * HID * 8, b2 + l * HID, l);
        pool_kernel<<<(N_NODESC + 63) / 64, 64>>>(batch_vec, l + 1);
    }
    final_kernel<<<NG, 256>>>(fc_W, fc_b, out);
}